// round 13
// baseline (speedup 1.0000x reference)
#include <cuda_runtime.h>

// ---------------------------------------------------------------------------
// LSTM_Model: T=512, B=4096, I=1, H=16, two LSTM layers, then MLP 16->64->32->1
// Reference output = MLP(h2[:, B-1, :]) -> only batch row B-1 matters.
//
// Kernel 1 (1 CTA, 4 warps, SMSP = wid%4):
//   wid 2 : layer-0 recurrence  (SMSP2, solo)
//   wid 3 : layer-1 recurrence  (SMSP3, solo)  -> writes h2 to global
//   wid 0 : layer-1 input-gate precompute (SMSP0, solo)
//   wid 1 : spare (barrier participant only)
// LSTM state (h,c) lives on LOWER half-warp; upper half computes f,o and
// ships sigma(f), sigma(o) via two xor-shfls that overlap the c-update chain.
// Kernel 2: MLP head, warp-per-row (128 blocks x 4 warps = 512 rows).
// ---------------------------------------------------------------------------

#define T_STEPS 512
#define H 16
#define BLK 16
#define NB (T_STEPS / BLK)
#define RING 32
#define FULL_MASK 0xffffffffu

typedef unsigned long long ull;

__device__ float g_h2[T_STEPS * H];   // layer-2 hidden states

__device__ __forceinline__ float tanh_fast(float x) {
    float y;
    asm("tanh.approx.f32 %0, %1;" : "=f"(y) : "f"(x));
    return y;
}
__device__ __forceinline__ ull pack2(float lo, float hi) {
    ull r;
    asm("mov.b64 %0, {%1, %2};" : "=l"(r) : "f"(lo), "f"(hi));
    return r;
}
__device__ __forceinline__ void unpack2(ull v, float& lo, float& hi) {
    asm("mov.b64 {%0, %1}, %2;" : "=f"(lo), "=f"(hi) : "l"(v));
}
__device__ __forceinline__ ull fma2(ull a, ull b, ull c) {
    ull d;
    asm("fma.rn.f32x2 %0, %1, %2, %3;" : "=l"(d) : "l"(a), "l"(b), "l"(c));
    return d;
}
__device__ __forceinline__ ull add2(ull a, ull b) {
    ull d;
    asm("add.rn.f32x2 %0, %1, %2;" : "=l"(d) : "l"(a), "l"(b));
    return d;
}

// One LSTM step, state on LOWER half (lanes 0-15).
//   lower lane j : gates i (row j,   pre-scaled 0.5) and g (row 32+j)
//   upper lane 16+j: gates f (row 16+j, 0.5) and o (row 48+j, 0.5)
// h_k broadcast from lane k. Upper ships sigma(f), sigma(o) to lower via two
// xor-16 shfls overlapping the P / c computation. Upper's c,h are garbage.
__device__ __forceinline__ void lstm_step(
    float aA, float aB,
    const float* __restrict__ wA,
    const float* __restrict__ wB,
    float cB, float dB,
    float& h, float& c)
{
    float s0 = aA,  s1 = 0.0f, s2 = 0.0f, s3 = 0.0f;
    float q0 = aB,  q1 = 0.0f, q2 = 0.0f, q3 = 0.0f;
#pragma unroll
    for (int k = 0; k < H; k += 4) {
        float h0 = __shfl_sync(FULL_MASK, h, k);
        float h1 = __shfl_sync(FULL_MASK, h, k + 1);
        float h2 = __shfl_sync(FULL_MASK, h, k + 2);
        float h3 = __shfl_sync(FULL_MASK, h, k + 3);
        s0 = fmaf(wA[k],     h0, s0);  q0 = fmaf(wB[k],     h0, q0);
        s1 = fmaf(wA[k + 1], h1, s1);  q1 = fmaf(wB[k + 1], h1, q1);
        s2 = fmaf(wA[k + 2], h2, s2);  q2 = fmaf(wB[k + 2], h2, q2);
        s3 = fmaf(wA[k + 3], h3, s3);  q3 = fmaf(wB[k + 3], h3, q3);
    }
    aA = (s0 + s1) + (s2 + s3);
    aB = (q0 + q1) + (q2 + q3);

    float A  = fmaf(0.5f, tanh_fast(aA), 0.5f);   // lower: sig(i), upper: sig(f)
    float Bv = fmaf(cB, tanh_fast(aB), dB);       // lower: tanh(g), upper: sig(o)

    float rF = __shfl_xor_sync(FULL_MASK, A, 16);  // lower receives sig(f)
    float rO = __shfl_xor_sync(FULL_MASK, Bv, 16); // lower receives sig(o)
    float P  = A * Bv;                             // lower: i*g
    c = fmaf(rF, c, P);                            // lower: sig(f)*c + i*g
    h = rO * tanh_fast(c);                         // lower: sig(o)*tanh(c)
}

// ---------------------------------------------------------------------------
__global__ void __launch_bounds__(128, 1) lstm_fused_kernel(
    const float* __restrict__ x, int B,
    const float* __restrict__ Wih0, const float* __restrict__ Whh0,
    const float* __restrict__ bih0, const float* __restrict__ bhh0,
    const float* __restrict__ Wih1, const float* __restrict__ Whh1,
    const float* __restrict__ bih1, const float* __restrict__ bhh1)
{
    __shared__ float xs[T_STEPS];                       // 2 KB
    __shared__ __align__(16) float h1r[RING * H];       // 2 KB
    __shared__ __align__(16) float xg1r[RING * 64];     // 8 KB

    const int tid  = threadIdx.x;
    const int wid  = tid >> 5;
    const int lane = tid & 31;
    const bool lower = (lane < 16);
    const float cB = lower ? 1.0f : 0.5f;
    const float dB = lower ? 0.0f : 0.5f;
    const float sB = lower ? 1.0f : 0.5f;   // B-gate weight pre-scale
    const int l = lane;

    // gather the single relevant batch row of x
    for (int t = tid; t < T_STEPS; t += 128)
        xs[t] = x[(size_t)t * B + (B - 1)];

    const bool isPre = (wid == 0);
    const bool isL0  = (wid == 2);
    const bool isL1  = (wid == 3);

    float wA[H], wB[H];                 // recurrence weights
    float uA[H], uB[H];                 // precompute: Wih1 rows
    float bA = 0.0f, bB = 0.0f, wiA = 0.0f, wiB = 0.0f;

    if (isL0) {
#pragma unroll
        for (int k = 0; k < H; k++) {
            wA[k] = 0.5f * Whh0[l * H + k];
            wB[k] = sB   * Whh0[(l + 32) * H + k];
        }
        wiA = 0.5f * Wih0[l];       wiB = sB * Wih0[l + 32];     // I = 1
        bA  = 0.5f * (bih0[l] + bhh0[l]);
        bB  = sB   * (bih0[l + 32] + bhh0[l + 32]);
    } else if (isPre) {
#pragma unroll
        for (int k = 0; k < H; k++) {
            uA[k] = 0.5f * Wih1[l * H + k];
            uB[k] = sB   * Wih1[(l + 32) * H + k];
        }
        bA = 0.5f * (bih1[l] + bhh1[l]);
        bB = sB   * (bih1[l + 32] + bhh1[l + 32]);
    } else if (isL1) {
#pragma unroll
        for (int k = 0; k < H; k++) {
            wA[k] = 0.5f * Whh1[l * H + k];
            wB[k] = sB   * Whh1[(l + 32) * H + k];
        }
    }
    __syncthreads();

    float h = 0.0f, c = 0.0f;

    // rounds: L0 does block blk, Pre blk-1, L1 blk-2
    for (int blk = 0; blk < NB + 2; blk++) {
        if (isL0) {
            if (blk < NB) {
                const int t0 = blk * BLK;
#pragma unroll 4
                for (int s = 0; s < BLK; s++) {
                    const int t = t0 + s;
                    const float xt = xs[t];
                    lstm_step(fmaf(wiA, xt, bA), fmaf(wiB, xt, bB),
                              wA, wB, cB, dB, h, c);
                    if (lower) h1r[(t & (RING-1)) * H + l] = h;
                }
            }
        } else if (isPre) {
            if (blk >= 1 && blk <= NB) {
                const int t0 = (blk - 1) * BLK;
#pragma unroll 4
                for (int s = 0; s < BLK; s++) {
                    const int t = t0 + s;
                    const float4* hp =
                        reinterpret_cast<const float4*>(h1r + (t & (RING-1)) * H);
                    float a = bA, b = bB;
#pragma unroll
                    for (int q = 0; q < 4; q++) {
                        float4 h4 = hp[q];
                        a = fmaf(uA[q*4+0], h4.x, a);  b = fmaf(uB[q*4+0], h4.x, b);
                        a = fmaf(uA[q*4+1], h4.y, a);  b = fmaf(uB[q*4+1], h4.y, b);
                        a = fmaf(uA[q*4+2], h4.z, a);  b = fmaf(uB[q*4+2], h4.z, b);
                        a = fmaf(uA[q*4+3], h4.w, a);  b = fmaf(uB[q*4+3], h4.w, b);
                    }
                    xg1r[(t & (RING-1)) * 64 + l]      = a;
                    xg1r[(t & (RING-1)) * 64 + l + 32] = b;
                }
            }
        } else if (isL1) {
            if (blk >= 2) {
                const int t0 = (blk - 2) * BLK;
#pragma unroll 4
                for (int s = 0; s < BLK; s++) {
                    const int t = t0 + s;
                    lstm_step(xg1r[(t & (RING-1)) * 64 + l],
                              xg1r[(t & (RING-1)) * 64 + l + 32],
                              wA, wB, cB, dB, h, c);
                    if (lower) g_h2[t * H + l] = h;   // off-chain STG
                }
            }
        }
        __syncthreads();   // uniform: all 128 threads, every round; drains STS
    }
}

// ---------------------------------------------------------------------------
// MLP head 16 -> 64 -> 32 -> 1, warp-per-row: 128 blocks x 4 warps = 512 rows.
// Per-lane weights in registers, z1 staged through shared, f32x2 math.
// ---------------------------------------------------------------------------
__global__ void __launch_bounds__(128) mlp_kernel(
    const float* __restrict__ W1, const float* __restrict__ b1,
    const float* __restrict__ W2, const float* __restrict__ b2,
    const float* __restrict__ W3, const float* __restrict__ b3,
    float* __restrict__ out)
{
    __shared__ __align__(16) float sz1[4][64];

    const int tid  = threadIdx.x;
    const int w    = tid >> 5;
    const int l    = tid & 31;
    const int r    = blockIdx.x * 4 + w;     // row 0..511

    // per-lane packed weights
    ull w1pA[8], w1pB[8], w2p[32];
#pragma unroll
    for (int k = 0; k < 8; k++) {
        w1pA[k] = pack2(W1[l * H + 2*k],        W1[l * H + 2*k + 1]);
        w1pB[k] = pack2(W1[(l + 32) * H + 2*k], W1[(l + 32) * H + 2*k + 1]);
    }
#pragma unroll
    for (int k = 0; k < 32; k++)
        w2p[k] = pack2(W2[l * 64 + 2*k], W2[l * 64 + 2*k + 1]);
    const float b1a = b1[l], b1b = b1[l + 32];
    const float b2l = b2[l], w3l = W3[l], b3v = b3[0];

    // load h row as packed f32x2
    const ulonglong2* hp = reinterpret_cast<const ulonglong2*>(g_h2 + r * H);
    ull hp8[8];
#pragma unroll
    for (int q = 0; q < 4; q++) {
        ulonglong2 v = hp[q];
        hp8[2*q] = v.x;  hp8[2*q+1] = v.y;
    }

    // z1 gates l and l+32
    ull aA0 = 0, aA1 = 0, aB0 = 0, aB1 = 0;
#pragma unroll
    for (int k = 0; k < 8; k += 2) {
        aA0 = fma2(w1pA[k],   hp8[k],   aA0);
        aA1 = fma2(w1pA[k+1], hp8[k+1], aA1);
        aB0 = fma2(w1pB[k],   hp8[k],   aB0);
        aB1 = fma2(w1pB[k+1], hp8[k+1], aB1);
    }
    float lo, hi;
    unpack2(add2(aA0, aA1), lo, hi);
    float z1a = fmaxf(b1a + lo + hi, 0.0f);
    unpack2(add2(aB0, aB1), lo, hi);
    float z1b = fmaxf(b1b + lo + hi, 0.0f);

    float* stage = sz1[w];
    stage[l]      = z1a;
    stage[l + 32] = z1b;
    __syncwarp();

    // z2 gate l: 64-dot via broadcast LDS.128 + packed fma
    const ulonglong2* zp = reinterpret_cast<const ulonglong2*>(stage);
    ull a0 = 0, a1 = 0, a2 = 0, a3 = 0;
#pragma unroll
    for (int q = 0; q < 16; q += 2) {
        ulonglong2 v0 = zp[q];
        ulonglong2 v1 = zp[q + 1];
        a0 = fma2(w2p[2*q],     v0.x, a0);
        a1 = fma2(w2p[2*q + 1], v0.y, a1);
        a2 = fma2(w2p[2*q + 2], v1.x, a2);
        a3 = fma2(w2p[2*q + 3], v1.y, a3);
    }
    unpack2(add2(add2(a0, a1), add2(a2, a3)), lo, hi);
    float z2v = fmaxf(b2l + lo + hi, 0.0f);

    // final dot: butterfly reduce of w3l * z2v
    float p = w3l * z2v;
    p += __shfl_xor_sync(FULL_MASK, p, 16);
    p += __shfl_xor_sync(FULL_MASK, p, 8);
    p += __shfl_xor_sync(FULL_MASK, p, 4);
    p += __shfl_xor_sync(FULL_MASK, p, 2);
    p += __shfl_xor_sync(FULL_MASK, p, 1);
    if (l == 0) out[r] = p + b3v;
}

// ---------------------------------------------------------------------------
extern "C" void kernel_launch(void* const* d_in, const int* in_sizes, int n_in,
                              void* d_out, int out_size)
{
    const float* x    = (const float*)d_in[0];
    const float* Wih0 = (const float*)d_in[1];
    const float* Whh0 = (const float*)d_in[2];
    const float* bih0 = (const float*)d_in[3];
    const float* bhh0 = (const float*)d_in[4];
    const float* Wih1 = (const float*)d_in[5];
    const float* Whh1 = (const float*)d_in[6];
    const float* bih1 = (const float*)d_in[7];
    const float* bhh1 = (const float*)d_in[8];
    const float* W1   = (const float*)d_in[9];
    const float* b1   = (const float*)d_in[10];
    const float* W2   = (const float*)d_in[11];
    const float* b2   = (const float*)d_in[12];
    const float* W3   = (const float*)d_in[13];
    const float* b3   = (const float*)d_in[14];

    const int B = in_sizes[0] / T_STEPS;   // 4096 (I = 1)

    lstm_fused_kernel<<<1, 128>>>(x, B,
        Wih0, Whh0, bih0, bhh0, Wih1, Whh1, bih1, bhh1);
    mlp_kernel<<<128, 128>>>(W1, b1, W2, b2, W3, b3, (float*)d_out);
}

// round 14
// speedup vs baseline: 1.0009x; 1.0009x over previous
#include <cuda_runtime.h>

// ---------------------------------------------------------------------------
// LSTM_Model: T=512, B=4096, I=1, H=16, two LSTM layers, then MLP 16->64->32->1
// Reference output = MLP(h2[:, B-1, :]) -> only batch row B-1 matters.
//
// Kernel 1 (1 CTA, 4 warps, SMSP = wid%4):
//   wid 2 : layer-0 recurrence  (SMSP2, solo)
//   wid 3 : layer-1 recurrence  (SMSP3, solo)  -> writes h2 to global
//   wid 0 : layer-1 input-gate precompute (SMSP0, solo)
//   wid 1 : spare (barrier participant only)
// Recurrent dot uses fma.rn.f32x2 with packed (wA_k, wB_k) weights: 16 FFMA2
// instead of 32 FFMA per step (fma-pipe time halved; packs ride the alu pipe).
// State (h,c) on LOWER half-warp; upper half ships sigma(f), sigma(o) via two
// xor-shfls overlapping the c-update.
// Kernel 2: MLP head, warp-per-row; __launch_bounds__(128,1) to prevent the
// register-cap spill seen in R13 (regs=32 -> local-memory thrash).
// ---------------------------------------------------------------------------

#define T_STEPS 512
#define H 16
#define BLK 16
#define NB (T_STEPS / BLK)
#define RING 32
#define FULL_MASK 0xffffffffu

typedef unsigned long long ull;

__device__ float g_h2[T_STEPS * H];   // layer-2 hidden states

__device__ __forceinline__ float tanh_fast(float x) {
    float y;
    asm("tanh.approx.f32 %0, %1;" : "=f"(y) : "f"(x));
    return y;
}
__device__ __forceinline__ ull pack2(float lo, float hi) {
    ull r;
    asm("mov.b64 %0, {%1, %2};" : "=l"(r) : "f"(lo), "f"(hi));
    return r;
}
__device__ __forceinline__ void unpack2(ull v, float& lo, float& hi) {
    asm("mov.b64 {%0, %1}, %2;" : "=f"(lo), "=f"(hi) : "l"(v));
}
__device__ __forceinline__ ull fma2(ull a, ull b, ull c) {
    ull d;
    asm("fma.rn.f32x2 %0, %1, %2, %3;" : "=l"(d) : "l"(a), "l"(b), "l"(c));
    return d;
}
__device__ __forceinline__ ull add2(ull a, ull b) {
    ull d;
    asm("add.rn.f32x2 %0, %1, %2;" : "=l"(d) : "l"(a), "l"(b));
    return d;
}

// One LSTM step, state on LOWER half (lanes 0-15).
//   lower lane j : gates i (row j,   pre-scaled 0.5) and g (row 32+j)
//   upper lane 16+j: gates f (row 16+j, 0.5) and o (row 48+j, 0.5)
// wAB[k] = (wA_k, wB_k) packed; accumulators hold (aA, aB) jointly.
// Accumulator k-grouping {0,4,8,12}... matches the scalar version exactly
// (bit-identical results).
__device__ __forceinline__ void lstm_step(
    float aAin, float aBin,
    const ull* __restrict__ wAB,
    float cB, float dB,
    float& h, float& c)
{
    ull acc0 = pack2(aAin, aBin), acc1 = 0ull, acc2 = 0ull, acc3 = 0ull;
#pragma unroll
    for (int k = 0; k < H; k += 4) {
        float h0 = __shfl_sync(FULL_MASK, h, k);
        float h1 = __shfl_sync(FULL_MASK, h, k + 1);
        float h2 = __shfl_sync(FULL_MASK, h, k + 2);
        float h3 = __shfl_sync(FULL_MASK, h, k + 3);
        acc0 = fma2(wAB[k],     pack2(h0, h0), acc0);
        acc1 = fma2(wAB[k + 1], pack2(h1, h1), acc1);
        acc2 = fma2(wAB[k + 2], pack2(h2, h2), acc2);
        acc3 = fma2(wAB[k + 3], pack2(h3, h3), acc3);
    }
    float aA, aB;
    unpack2(add2(add2(acc0, acc1), add2(acc2, acc3)), aA, aB);

    float A  = fmaf(0.5f, tanh_fast(aA), 0.5f);   // lower: sig(i), upper: sig(f)
    float Bv = fmaf(cB, tanh_fast(aB), dB);       // lower: tanh(g), upper: sig(o)

    float rF = __shfl_xor_sync(FULL_MASK, A, 16);  // lower receives sig(f)
    float rO = __shfl_xor_sync(FULL_MASK, Bv, 16); // lower receives sig(o)
    float P  = A * Bv;                             // lower: i*g
    c = fmaf(rF, c, P);                            // lower: sig(f)*c + i*g
    h = rO * tanh_fast(c);                         // lower: sig(o)*tanh(c)
}

// ---------------------------------------------------------------------------
__global__ void __launch_bounds__(128, 1) lstm_fused_kernel(
    const float* __restrict__ x, int B,
    const float* __restrict__ Wih0, const float* __restrict__ Whh0,
    const float* __restrict__ bih0, const float* __restrict__ bhh0,
    const float* __restrict__ Wih1, const float* __restrict__ Whh1,
    const float* __restrict__ bih1, const float* __restrict__ bhh1)
{
    __shared__ float xs[T_STEPS];                       // 2 KB
    __shared__ __align__(16) float h1r[RING * H];       // 2 KB
    __shared__ __align__(16) float xg1r[RING * 64];     // 8 KB

    const int tid  = threadIdx.x;
    const int wid  = tid >> 5;
    const int lane = tid & 31;
    const bool lower = (lane < 16);
    const float cB = lower ? 1.0f : 0.5f;
    const float dB = lower ? 0.0f : 0.5f;
    const float sB = lower ? 1.0f : 0.5f;   // B-gate weight pre-scale
    const int l = lane;

    // gather the single relevant batch row of x
    for (int t = tid; t < T_STEPS; t += 128)
        xs[t] = x[(size_t)t * B + (B - 1)];

    const bool isPre = (wid == 0);
    const bool isL0  = (wid == 2);
    const bool isL1  = (wid == 3);

    ull  wAB[H];                        // packed recurrence weights
    float uA[H], uB[H];                 // precompute: Wih1 rows
    float bA = 0.0f, bB = 0.0f, wiA = 0.0f, wiB = 0.0f;

    if (isL0) {
#pragma unroll
        for (int k = 0; k < H; k++)
            wAB[k] = pack2(0.5f * Whh0[l * H + k],
                           sB   * Whh0[(l + 32) * H + k]);
        wiA = 0.5f * Wih0[l];       wiB = sB * Wih0[l + 32];     // I = 1
        bA  = 0.5f * (bih0[l] + bhh0[l]);
        bB  = sB   * (bih0[l + 32] + bhh0[l + 32]);
    } else if (isPre) {
#pragma unroll
        for (int k = 0; k < H; k++) {
            uA[k] = 0.5f * Wih1[l * H + k];
            uB[k] = sB   * Wih1[(l + 32) * H + k];
        }
        bA = 0.5f * (bih1[l] + bhh1[l]);
        bB = sB   * (bih1[l + 32] + bhh1[l + 32]);
    } else if (isL1) {
#pragma unroll
        for (int k = 0; k < H; k++)
            wAB[k] = pack2(0.5f * Whh1[l * H + k],
                           sB   * Whh1[(l + 32) * H + k]);
    }
    __syncthreads();

    float h = 0.0f, c = 0.0f;

    // rounds: L0 does block blk, Pre blk-1, L1 blk-2
    for (int blk = 0; blk < NB + 2; blk++) {
        if (isL0) {
            if (blk < NB) {
                const int t0 = blk * BLK;
#pragma unroll 4
                for (int s = 0; s < BLK; s++) {
                    const int t = t0 + s;
                    const float xt = xs[t];
                    lstm_step(fmaf(wiA, xt, bA), fmaf(wiB, xt, bB),
                              wAB, cB, dB, h, c);
                    if (lower) h1r[(t & (RING-1)) * H + l] = h;
                }
            }
        } else if (isPre) {
            if (blk >= 1 && blk <= NB) {
                const int t0 = (blk - 1) * BLK;
#pragma unroll 4
                for (int s = 0; s < BLK; s++) {
                    const int t = t0 + s;
                    const float4* hp =
                        reinterpret_cast<const float4*>(h1r + (t & (RING-1)) * H);
                    float a = bA, b = bB;
#pragma unroll
                    for (int q = 0; q < 4; q++) {
                        float4 h4 = hp[q];
                        a = fmaf(uA[q*4+0], h4.x, a);  b = fmaf(uB[q*4+0], h4.x, b);
                        a = fmaf(uA[q*4+1], h4.y, a);  b = fmaf(uB[q*4+1], h4.y, b);
                        a = fmaf(uA[q*4+2], h4.z, a);  b = fmaf(uB[q*4+2], h4.z, b);
                        a = fmaf(uA[q*4+3], h4.w, a);  b = fmaf(uB[q*4+3], h4.w, b);
                    }
                    xg1r[(t & (RING-1)) * 64 + l]      = a;
                    xg1r[(t & (RING-1)) * 64 + l + 32] = b;
                }
            }
        } else if (isL1) {
            if (blk >= 2) {
                const int t0 = (blk - 2) * BLK;
#pragma unroll 4
                for (int s = 0; s < BLK; s++) {
                    const int t = t0 + s;
                    lstm_step(xg1r[(t & (RING-1)) * 64 + l],
                              xg1r[(t & (RING-1)) * 64 + l + 32],
                              wAB, cB, dB, h, c);
                    if (lower) g_h2[t * H + l] = h;   // off-chain STG
                }
            }
        }
        __syncthreads();   // uniform: all 128 threads, every round; drains STS
    }
}

// ---------------------------------------------------------------------------
// MLP head 16 -> 64 -> 32 -> 1, warp-per-row: 128 blocks x 4 warps = 512 rows.
// __launch_bounds__(128, 1): full register budget (R13's implicit cap spilled
// w2p to local memory and cost 10us).
// ---------------------------------------------------------------------------
__global__ void __launch_bounds__(128, 1) mlp_kernel(
    const float* __restrict__ W1, const float* __restrict__ b1,
    const float* __restrict__ W2, const float* __restrict__ b2,
    const float* __restrict__ W3, const float* __restrict__ b3,
    float* __restrict__ out)
{
    __shared__ __align__(16) float sz1[4][64];

    const int tid  = threadIdx.x;
    const int w    = tid >> 5;
    const int l    = tid & 31;
    const int r    = blockIdx.x * 4 + w;     // row 0..511

    // per-lane packed weights
    ull w1pA[8], w1pB[8], w2p[32];
#pragma unroll
    for (int k = 0; k < 8; k++) {
        w1pA[k] = pack2(W1[l * H + 2*k],        W1[l * H + 2*k + 1]);
        w1pB[k] = pack2(W1[(l + 32) * H + 2*k], W1[(l + 32) * H + 2*k + 1]);
    }
#pragma unroll
    for (int k = 0; k < 32; k++)
        w2p[k] = pack2(W2[l * 64 + 2*k], W2[l * 64 + 2*k + 1]);
    const float b1a = b1[l], b1b = b1[l + 32];
    const float b2l = b2[l], w3l = W3[l], b3v = b3[0];

    // load h row as packed f32x2
    const ulonglong2* hp = reinterpret_cast<const ulonglong2*>(g_h2 + r * H);
    ull hp8[8];
#pragma unroll
    for (int q = 0; q < 4; q++) {
        ulonglong2 v = hp[q];
        hp8[2*q] = v.x;  hp8[2*q+1] = v.y;
    }

    // z1 gates l and l+32
    ull aA0 = 0, aA1 = 0, aB0 = 0, aB1 = 0;
#pragma unroll
    for (int k = 0; k < 8; k += 2) {
        aA0 = fma2(w1pA[k],   hp8[k],   aA0);
        aA1 = fma2(w1pA[k+1], hp8[k+1], aA1);
        aB0 = fma2(w1pB[k],   hp8[k],   aB0);
        aB1 = fma2(w1pB[k+1], hp8[k+1], aB1);
    }
    float lo, hi;
    unpack2(add2(aA0, aA1), lo, hi);
    float z1a = fmaxf(b1a + lo + hi, 0.0f);
    unpack2(add2(aB0, aB1), lo, hi);
    float z1b = fmaxf(b1b + lo + hi, 0.0f);

    float* stage = sz1[w];
    stage[l]      = z1a;
    stage[l + 32] = z1b;
    __syncwarp();

    // z2 gate l: 64-dot via broadcast LDS.128 + packed fma
    const ulonglong2* zp = reinterpret_cast<const ulonglong2*>(stage);
    ull a0 = 0, a1 = 0, a2 = 0, a3 = 0;
#pragma unroll
    for (int q = 0; q < 16; q += 2) {
        ulonglong2 v0 = zp[q];
        ulonglong2 v1 = zp[q + 1];
        a0 = fma2(w2p[2*q],     v0.x, a0);
        a1 = fma2(w2p[2*q + 1], v0.y, a1);
        a2 = fma2(w2p[2*q + 2], v1.x, a2);
        a3 = fma2(w2p[2*q + 3], v1.y, a3);
    }
    unpack2(add2(add2(a0, a1), add2(a2, a3)), lo, hi);
    float z2v = fmaxf(b2l + lo + hi, 0.0f);

    // final dot: butterfly reduce of w3l * z2v
    float p = w3l * z2v;
    p += __shfl_xor_sync(FULL_MASK, p, 16);
    p += __shfl_xor_sync(FULL_MASK, p, 8);
    p += __shfl_xor_sync(FULL_MASK, p, 4);
    p += __shfl_xor_sync(FULL_MASK, p, 2);
    p += __shfl_xor_sync(FULL_MASK, p, 1);
    if (l == 0) out[r] = p + b3v;
}

// ---------------------------------------------------------------------------
extern "C" void kernel_launch(void* const* d_in, const int* in_sizes, int n_in,
                              void* d_out, int out_size)
{
    const float* x    = (const float*)d_in[0];
    const float* Wih0 = (const float*)d_in[1];
    const float* Whh0 = (const float*)d_in[2];
    const float* bih0 = (const float*)d_in[3];
    const float* bhh0 = (const float*)d_in[4];
    const float* Wih1 = (const float*)d_in[5];
    const float* Whh1 = (const float*)d_in[6];
    const float* bih1 = (const float*)d_in[7];
    const float* bhh1 = (const float*)d_in[8];
    const float* W1   = (const float*)d_in[9];
    const float* b1   = (const float*)d_in[10];
    const float* W2   = (const float*)d_in[11];
    const float* b2   = (const float*)d_in[12];
    const float* W3   = (const float*)d_in[13];
    const float* b3   = (const float*)d_in[14];

    const int B = in_sizes[0] / T_STEPS;   // 4096 (I = 1)

    lstm_fused_kernel<<<1, 128>>>(x, B,
        Wih0, Whh0, bih0, bhh0, Wih1, Whh1, bih1, bhh1);
    mlp_kernel<<<128, 128>>>(W1, b1, W2, b2, W3, b3, (float*)d_out);
}

// round 15
// speedup vs baseline: 1.1240x; 1.1231x over previous
#include <cuda_runtime.h>

// ---------------------------------------------------------------------------
// LSTM_Model: T=512, B=4096, I=1, H=16, two LSTM layers, then MLP 16->64->32->1
// Reference output = MLP(h2[:, B-1, :]) -> only batch row B-1 matters.
//
// Kernel 1 (1 CTA, 3 warps, SMSP = wid%4):
//   wid 0 : layer-1 input-gate precompute (SMSP0)
//   wid 1 : layer-0 recurrence  (SMSP1)
//   wid 2 : layer-1 recurrence  (SMSP2)  -> writes h2 to global
// xg1 handoff stored as adjacent (a,b) pairs: 1 STS.64 / 1 LDS.64 per step.
// Kernel 2: MLP head, warp-per-row, weights staged in shared with odd-padded
// rows (17/65) so per-lane row reads are bank-conflict-free. Fixes R14's
// L1tex sector thrash (strided per-lane LDG of W2 rows).
// ---------------------------------------------------------------------------

#define T_STEPS 512
#define H 16
#define BLK 16
#define NB (T_STEPS / BLK)
#define RING 32
#define FULL_MASK 0xffffffffu

typedef unsigned long long ull;

__device__ float g_h2[T_STEPS * H];   // layer-2 hidden states

__device__ __forceinline__ float tanh_fast(float x) {
    float y;
    asm("tanh.approx.f32 %0, %1;" : "=f"(y) : "f"(x));
    return y;
}
__device__ __forceinline__ ull pack2(float lo, float hi) {
    ull r;
    asm("mov.b64 %0, {%1, %2};" : "=l"(r) : "f"(lo), "f"(hi));
    return r;
}
__device__ __forceinline__ void unpack2(ull v, float& lo, float& hi) {
    asm("mov.b64 {%0, %1}, %2;" : "=f"(lo), "=f"(hi) : "l"(v));
}
__device__ __forceinline__ ull fma2(ull a, ull b, ull c) {
    ull d;
    asm("fma.rn.f32x2 %0, %1, %2, %3;" : "=l"(d) : "l"(a), "l"(b), "l"(c));
    return d;
}
__device__ __forceinline__ ull add2(ull a, ull b) {
    ull d;
    asm("add.rn.f32x2 %0, %1, %2;" : "=l"(d) : "l"(a), "l"(b));
    return d;
}

// One LSTM step, state on LOWER half (lanes 0-15).
//   lower lane j : gates i (row j, pre-scaled 0.5) and g (row 32+j)
//   upper lane 16+j: gates f (row 16+j, 0.5) and o (row 48+j, 0.5)
// wAB[k] = (wA_k, wB_k) packed; accumulator grouping matches scalar version.
__device__ __forceinline__ void lstm_step(
    float aAin, float aBin,
    const ull* __restrict__ wAB,
    float cB, float dB,
    float& h, float& c)
{
    ull acc0 = pack2(aAin, aBin), acc1 = 0ull, acc2 = 0ull, acc3 = 0ull;
#pragma unroll
    for (int k = 0; k < H; k += 4) {
        float h0 = __shfl_sync(FULL_MASK, h, k);
        float h1 = __shfl_sync(FULL_MASK, h, k + 1);
        float h2 = __shfl_sync(FULL_MASK, h, k + 2);
        float h3 = __shfl_sync(FULL_MASK, h, k + 3);
        acc0 = fma2(wAB[k],     pack2(h0, h0), acc0);
        acc1 = fma2(wAB[k + 1], pack2(h1, h1), acc1);
        acc2 = fma2(wAB[k + 2], pack2(h2, h2), acc2);
        acc3 = fma2(wAB[k + 3], pack2(h3, h3), acc3);
    }
    float aA, aB;
    unpack2(add2(add2(acc0, acc1), add2(acc2, acc3)), aA, aB);

    float A  = fmaf(0.5f, tanh_fast(aA), 0.5f);   // lower: sig(i), upper: sig(f)
    float Bv = fmaf(cB, tanh_fast(aB), dB);       // lower: tanh(g), upper: sig(o)

    float rF = __shfl_xor_sync(FULL_MASK, A, 16);  // lower receives sig(f)
    float rO = __shfl_xor_sync(FULL_MASK, Bv, 16); // lower receives sig(o)
    float P  = A * Bv;                             // lower: i*g
    c = fmaf(rF, c, P);                            // lower: sig(f)*c + i*g
    h = rO * tanh_fast(c);                         // lower: sig(o)*tanh(c)
}

// ---------------------------------------------------------------------------
__global__ void __launch_bounds__(96, 1) lstm_fused_kernel(
    const float* __restrict__ x, int B,
    const float* __restrict__ Wih0, const float* __restrict__ Whh0,
    const float* __restrict__ bih0, const float* __restrict__ bhh0,
    const float* __restrict__ Wih1, const float* __restrict__ Whh1,
    const float* __restrict__ bih1, const float* __restrict__ bhh1)
{
    __shared__ float xs[T_STEPS];                       // 2 KB
    __shared__ __align__(16) float h1r[RING * H];       // 2 KB
    __shared__ __align__(16) float xg1r[RING * 64];     // 8 KB, (a,b) pairs at 2l
    // gate j at xg1r[row*64 + 2*j], gate j+32 at xg1r[row*64 + 2*j + 1]

    const int tid  = threadIdx.x;
    const int wid  = tid >> 5;
    const int lane = tid & 31;
    const bool lower = (lane < 16);
    const float cB = lower ? 1.0f : 0.5f;
    const float dB = lower ? 0.0f : 0.5f;
    const float sB = lower ? 1.0f : 0.5f;   // B-gate weight pre-scale
    const int l = lane;

    // gather the single relevant batch row of x
    for (int t = tid; t < T_STEPS; t += 96)
        xs[t] = x[(size_t)t * B + (B - 1)];

    const bool isPre = (wid == 0);
    const bool isL0  = (wid == 1);
    const bool isL1  = (wid == 2);

    ull  wAB[H];                        // packed recurrence weights
    float uA[H], uB[H];                 // precompute: Wih1 rows
    float bA = 0.0f, bB = 0.0f, wiA = 0.0f, wiB = 0.0f;

    if (isL0) {
#pragma unroll
        for (int k = 0; k < H; k++)
            wAB[k] = pack2(0.5f * Whh0[l * H + k],
                           sB   * Whh0[(l + 32) * H + k]);
        wiA = 0.5f * Wih0[l];       wiB = sB * Wih0[l + 32];     // I = 1
        bA  = 0.5f * (bih0[l] + bhh0[l]);
        bB  = sB   * (bih0[l + 32] + bhh0[l + 32]);
    } else if (isPre) {
#pragma unroll
        for (int k = 0; k < H; k++) {
            uA[k] = 0.5f * Wih1[l * H + k];
            uB[k] = sB   * Wih1[(l + 32) * H + k];
        }
        bA = 0.5f * (bih1[l] + bhh1[l]);
        bB = sB   * (bih1[l + 32] + bhh1[l + 32]);
    } else if (isL1) {
#pragma unroll
        for (int k = 0; k < H; k++)
            wAB[k] = pack2(0.5f * Whh1[l * H + k],
                           sB   * Whh1[(l + 32) * H + k]);
    }
    __syncthreads();

    float h = 0.0f, c = 0.0f;

    // rounds: L0 does block blk, Pre blk-1, L1 blk-2
    for (int blk = 0; blk < NB + 2; blk++) {
        if (isL0) {
            if (blk < NB) {
                const int t0 = blk * BLK;
#pragma unroll 4
                for (int s = 0; s < BLK; s++) {
                    const int t = t0 + s;
                    const float xt = xs[t];
                    lstm_step(fmaf(wiA, xt, bA), fmaf(wiB, xt, bB),
                              wAB, cB, dB, h, c);
                    if (lower) h1r[(t & (RING-1)) * H + l] = h;
                }
            }
        } else if (isPre) {
            if (blk >= 1 && blk <= NB) {
                const int t0 = (blk - 1) * BLK;
#pragma unroll 4
                for (int s = 0; s < BLK; s++) {
                    const int t = t0 + s;
                    const float4* hp =
                        reinterpret_cast<const float4*>(h1r + (t & (RING-1)) * H);
                    float a = bA, b = bB;
#pragma unroll
                    for (int q = 0; q < 4; q++) {
                        float4 h4 = hp[q];
                        a = fmaf(uA[q*4+0], h4.x, a);  b = fmaf(uB[q*4+0], h4.x, b);
                        a = fmaf(uA[q*4+1], h4.y, a);  b = fmaf(uB[q*4+1], h4.y, b);
                        a = fmaf(uA[q*4+2], h4.z, a);  b = fmaf(uB[q*4+2], h4.z, b);
                        a = fmaf(uA[q*4+3], h4.w, a);  b = fmaf(uB[q*4+3], h4.w, b);
                    }
                    // paired store: one STS.64 per lane, conflict-free
                    reinterpret_cast<float2*>(xg1r + (t & (RING-1)) * 64)[l] =
                        make_float2(a, b);
                }
            }
        } else if (isL1) {
            if (blk >= 2) {
                const int t0 = (blk - 2) * BLK;
#pragma unroll 4
                for (int s = 0; s < BLK; s++) {
                    const int t = t0 + s;
                    // paired load: one LDS.64, prefetchable (no h dependence)
                    float2 ab =
                        reinterpret_cast<const float2*>(xg1r + (t & (RING-1)) * 64)[l];
                    lstm_step(ab.x, ab.y, wAB, cB, dB, h, c);
                    if (lower) g_h2[t * H + l] = h;   // off-chain STG
                }
            }
        }
        __syncthreads();   // uniform: all 96 threads, every round; drains STS
    }
}

// ---------------------------------------------------------------------------
// MLP head 16 -> 64 -> 32 -> 1, warp-per-row: 128 blocks x 4 warps = 512 rows.
// Weights staged in shared with odd row padding (conflict-free per-lane rows):
//   sW1: 64 rows x 17  (17l mod 32 distinct)
//   sW2: 32 rows x 65  (65l mod 32 = l, distinct)
// ---------------------------------------------------------------------------
__global__ void __launch_bounds__(128, 1) mlp_kernel(
    const float* __restrict__ W1, const float* __restrict__ b1,
    const float* __restrict__ W2, const float* __restrict__ b2,
    const float* __restrict__ W3, const float* __restrict__ b3,
    float* __restrict__ out)
{
    __shared__ float sW1[64 * 17];           // 4.25 KB
    __shared__ float sW2[32 * 65];           // 8.125 KB
    __shared__ float sb1[64], sb2[32], sW3s[32];
    __shared__ __align__(16) float sz1[4][64];

    const int tid  = threadIdx.x;
    const int w    = tid >> 5;
    const int l    = tid & 31;
    const int r    = blockIdx.x * 4 + w;     // row 0..511

    // coalesced staging (consecutive tid -> consecutive global)
    for (int idx = tid; idx < 64 * H; idx += 128)
        sW1[(idx >> 4) * 17 + (idx & 15)] = W1[idx];
    for (int idx = tid; idx < 32 * 64; idx += 128)
        sW2[(idx >> 6) * 65 + (idx & 63)] = W2[idx];
    if (tid < 64) sb1[tid] = b1[tid];
    else if (tid < 96)  sb2[tid - 64] = b2[tid - 64];
    else                sW3s[tid - 96] = W3[tid - 96];
    __syncthreads();

    // per-lane packed weights from conflict-free smem rows
    ull w1pA[8], w1pB[8], w2p[32];
    const float* r1a = sW1 + l * 17;
    const float* r1b = sW1 + (l + 32) * 17;
#pragma unroll
    for (int k = 0; k < 8; k++) {
        w1pA[k] = pack2(r1a[2*k], r1a[2*k + 1]);
        w1pB[k] = pack2(r1b[2*k], r1b[2*k + 1]);
    }
    const float* r2 = sW2 + l * 65;
#pragma unroll
    for (int k = 0; k < 32; k++)
        w2p[k] = pack2(r2[2*k], r2[2*k + 1]);
    const float b1a = sb1[l], b1b = sb1[l + 32];
    const float b2l = sb2[l], w3l = sW3s[l], b3v = b3[0];

    // load h row as packed f32x2
    const ulonglong2* hp = reinterpret_cast<const ulonglong2*>(g_h2 + r * H);
    ull hp8[8];
#pragma unroll
    for (int q = 0; q < 4; q++) {
        ulonglong2 v = hp[q];
        hp8[2*q] = v.x;  hp8[2*q+1] = v.y;
    }

    // z1 gates l and l+32
    ull aA0 = 0, aA1 = 0, aB0 = 0, aB1 = 0;
#pragma unroll
    for (int k = 0; k < 8; k += 2) {
        aA0 = fma2(w1pA[k],   hp8[k],   aA0);
        aA1 = fma2(w1pA[k+1], hp8[k+1], aA1);
        aB0 = fma2(w1pB[k],   hp8[k],   aB0);
        aB1 = fma2(w1pB[k+1], hp8[k+1], aB1);
    }
    float lo, hi;
    unpack2(add2(aA0, aA1), lo, hi);
    float z1a = fmaxf(b1a + lo + hi, 0.0f);
    unpack2(add2(aB0, aB1), lo, hi);
    float z1b = fmaxf(b1b + lo + hi, 0.0f);

    float* stage = sz1[w];
    stage[l]      = z1a;
    stage[l + 32] = z1b;
    __syncwarp();

    // z2 gate l: 64-dot via broadcast LDS.128 + packed fma
    const ulonglong2* zp = reinterpret_cast<const ulonglong2*>(stage);
    ull a0 = 0, a1 = 0, a2 = 0, a3 = 0;
#pragma unroll
    for (int q = 0; q < 16; q += 2) {
        ulonglong2 v0 = zp[q];
        ulonglong2 v1 = zp[q + 1];
        a0 = fma2(w2p[2*q],     v0.x, a0);
        a1 = fma2(w2p[2*q + 1], v0.y, a1);
        a2 = fma2(w2p[2*q + 2], v1.x, a2);
        a3 = fma2(w2p[2*q + 3], v1.y, a3);
    }
    unpack2(add2(add2(a0, a1), add2(a2, a3)), lo, hi);
    float z2v = fmaxf(b2l + lo + hi, 0.0f);

    // final dot: butterfly reduce of w3l * z2v
    float p = w3l * z2v;
    p += __shfl_xor_sync(FULL_MASK, p, 16);
    p += __shfl_xor_sync(FULL_MASK, p, 8);
    p += __shfl_xor_sync(FULL_MASK, p, 4);
    p += __shfl_xor_sync(FULL_MASK, p, 2);
    p += __shfl_xor_sync(FULL_MASK, p, 1);
    if (l == 0) out[r] = p + b3v;
}

// ---------------------------------------------------------------------------
extern "C" void kernel_launch(void* const* d_in, const int* in_sizes, int n_in,
                              void* d_out, int out_size)
{
    const float* x    = (const float*)d_in[0];
    const float* Wih0 = (const float*)d_in[1];
    const float* Whh0 = (const float*)d_in[2];
    const float* bih0 = (const float*)d_in[3];
    const float* bhh0 = (const float*)d_in[4];
    const float* Wih1 = (const float*)d_in[5];
    const float* Whh1 = (const float*)d_in[6];
    const float* bih1 = (const float*)d_in[7];
    const float* bhh1 = (const float*)d_in[8];
    const float* W1   = (const float*)d_in[9];
    const float* b1   = (const float*)d_in[10];
    const float* W2   = (const float*)d_in[11];
    const float* b2   = (const float*)d_in[12];
    const float* W3   = (const float*)d_in[13];
    const float* b3   = (const float*)d_in[14];

    const int B = in_sizes[0] / T_STEPS;   // 4096 (I = 1)

    lstm_fused_kernel<<<1, 96>>>(x, B,
        Wih0, Whh0, bih0, bhh0, Wih1, Whh1, bih1, bhh1);
    mlp_kernel<<<128, 128>>>(W1, b1, W2, b2, W3, b3, (float*)d_out);
}